// round 15
// baseline (speedup 1.0000x reference)
#include <cuda_runtime.h>
#include <cuda_bf16.h>

#define N_PAD   3000
#define N_REAL  2500
#define F_IN    1024
#define H1      256
#define OUTD    128
#define GATES_N 384   // 3 live gates (i, c, o) x 128 — forget gate dead (C_prev=0)
#define SLOT    256   // per-node CSR capacity (max degree ~137, 15-sigma safe)
#define CSR_BLOCKS 128

// Scratch (device globals — no allocation allowed).  g_cur is zero-initialized
// at module load; gather_kernel re-zeroes it at the end of every call, so each
// invocation (and each graph replay) sees zeros.
__device__ float           g_xh  [N_PAD * H1];        // relu(fc0(x_pad)) fp32 (GEMM2 operand)
__device__ __nv_bfloat162  g_xhb [N_PAD * H1 / 2];    // same, bf16 (gather operand)
__device__ float           g_agg [N_PAD * H1];        // mean-aggregated neighbors
__device__ float           g_gate[N_PAD * GATES_N];   // pre-activation gates (i,c,o packed)
__device__ int             g_cur [N_PAD];             // per-node fill cursor == degree
__device__ int             g_csr [N_PAD * SLOT];      // slotted CSR (stride 256 per node)

// ---------------------------------------------------------------------------
__device__ __forceinline__ unsigned f2tf32(float f) {
    unsigned u;
    asm("cvt.rna.tf32.f32 %0, %1;" : "=r"(u) : "f"(f));
    return u;
}

__device__ __forceinline__ void mma_tf32(float* c, const unsigned* a, const unsigned* b) {
    asm volatile(
        "mma.sync.aligned.m16n8k8.row.col.f32.tf32.tf32.f32 "
        "{%0,%1,%2,%3}, {%4,%5,%6,%7}, {%8,%9}, {%0,%1,%2,%3};\n"
        : "+f"(c[0]), "+f"(c[1]), "+f"(c[2]), "+f"(c[3])
        : "r"(a[0]), "r"(a[1]), "r"(a[2]), "r"(a[3]), "r"(b[0]), "r"(b[1]));
}

// ---------------------------------------------------------------------------
// Shared-memory strides chosen for conflict-free fragment loads.
#define ASTRIDE 40
#define BSTRIDE 72
#define A_TILE  (32 * ASTRIDE)     // 32-row M tile
#define B_TILE  (32 * BSTRIDE)

// GEMM1: xh[m,n] = relu(sum_k x[m,k]*w[n,k] + b[n]) for m<2500; padded rows
// 2500..2999 have zero A so the result is exactly relu(b[n]) — grid covers
// all 3000+ rows, no separate init kernel.
// 32x64x32 block tile, 128 threads (4 warps, 2x2, warp tile 16x32).
// Double-buffered, one sync per k-iter, register prefetch during MMA.
// Grid is 2x the 64-row version -> ~4 blocks/SM -> latency actually hidden.
__global__ void gemm1_kernel(const float* __restrict__ x,
                             const float* __restrict__ w,
                             const float* __restrict__ bias) {
    __shared__ unsigned As[2 * A_TILE];
    __shared__ unsigned Bs[2 * B_TILE];
    const int bm = blockIdx.y * 32;
    const int bn = blockIdx.x * 64;
    const int tid = threadIdx.x;
    const int warp = tid >> 5, lane = tid & 31;
    const int wm = warp >> 1, wn = warp & 1;
    const int gid = lane >> 2, tig = lane & 3;

    float acc[4][4];
#pragma unroll
    for (int nt = 0; nt < 4; nt++)
#pragma unroll
        for (int r = 0; r < 4; r++) acc[nt][r] = 0.f;

    const int r0 = tid >> 3;        // 0..15
    const int c8 = tid & 7;         // 0..7 (float4-column)
    const int nb = tid & 63;        // 0..63 (B row = output col)
    const int cb = tid >> 6;        // 0..1

    float4 ra[2], rb[4];
#pragma unroll
    for (int rr = 0; rr < 2; rr++) {
        int gm = bm + r0 + rr * 16;
        ra[rr] = make_float4(0.f, 0.f, 0.f, 0.f);
        if (gm < N_REAL)
            ra[rr] = *(const float4*)(x + (size_t)gm * F_IN + 4 * c8);
    }
#pragma unroll
    for (int i = 0; i < 4; i++)
        rb[i] = *(const float4*)(w + (size_t)(bn + nb) * F_IN + 4 * (cb * 4 + i));

    for (int k0 = 0; k0 < F_IN; k0 += 32) {
        const int buf = (k0 >> 5) & 1;
        unsigned* Ab = As + buf * A_TILE;
        unsigned* Bb = Bs + buf * B_TILE;
#pragma unroll
        for (int rr = 0; rr < 2; rr++) {
            uint4 u = make_uint4(f2tf32(ra[rr].x), f2tf32(ra[rr].y),
                                 f2tf32(ra[rr].z), f2tf32(ra[rr].w));
            *(uint4*)&Ab[(r0 + rr * 16) * ASTRIDE + 4 * c8] = u;
        }
#pragma unroll
        for (int i = 0; i < 4; i++) {
            int c = cb * 4 + i;
            Bb[(4 * c + 0) * BSTRIDE + nb] = f2tf32(rb[i].x);
            Bb[(4 * c + 1) * BSTRIDE + nb] = f2tf32(rb[i].y);
            Bb[(4 * c + 2) * BSTRIDE + nb] = f2tf32(rb[i].z);
            Bb[(4 * c + 3) * BSTRIDE + nb] = f2tf32(rb[i].w);
        }
        __syncthreads();
        if (k0 + 32 < F_IN) {
            int kn = k0 + 32;
#pragma unroll
            for (int rr = 0; rr < 2; rr++) {
                int gm = bm + r0 + rr * 16;
                ra[rr] = make_float4(0.f, 0.f, 0.f, 0.f);
                if (gm < N_REAL)
                    ra[rr] = *(const float4*)(x + (size_t)gm * F_IN + kn + 4 * c8);
            }
#pragma unroll
            for (int i = 0; i < 4; i++)
                rb[i] = *(const float4*)(w + (size_t)(bn + nb) * F_IN + kn + 4 * (cb * 4 + i));
        }

#pragma unroll
        for (int ks = 0; ks < 4; ks++) {
            int kk = ks * 8;
            unsigned a[4], b[4][2];
            const int ar = wm * 16;
            a[0] = Ab[(ar + gid) * ASTRIDE + kk + tig];
            a[1] = Ab[(ar + gid + 8) * ASTRIDE + kk + tig];
            a[2] = Ab[(ar + gid) * ASTRIDE + kk + tig + 4];
            a[3] = Ab[(ar + gid + 8) * ASTRIDE + kk + tig + 4];
#pragma unroll
            for (int nt = 0; nt < 4; nt++) {
                int nc = wn * 32 + nt * 8 + gid;
                b[nt][0] = Bb[(kk + tig) * BSTRIDE + nc];
                b[nt][1] = Bb[(kk + tig + 4) * BSTRIDE + nc];
            }
#pragma unroll
            for (int nt = 0; nt < 4; nt++)
                mma_tf32(acc[nt], a, b[nt]);
        }
        __syncthreads();
    }

    {
        int mrow0 = bm + wm * 16 + gid;
#pragma unroll
        for (int nt = 0; nt < 4; nt++) {
            int ncol = bn + wn * 32 + nt * 8 + 2 * tig;     // even
            float b0 = bias[ncol], b1 = bias[ncol + 1];
            if (mrow0 < N_PAD) {
                float v0 = acc[nt][0] + b0, v1 = acc[nt][1] + b1;
                v0 = v0 > 0.f ? v0 : 0.f;  v1 = v1 > 0.f ? v1 : 0.f;
                g_xh[mrow0 * H1 + ncol]     = v0;
                g_xh[mrow0 * H1 + ncol + 1] = v1;
                g_xhb[(mrow0 * H1 + ncol) >> 1] = __floats2bfloat162_rn(v0, v1);
            }
            if (mrow0 + 8 < N_PAD) {
                float v2 = acc[nt][2] + b0, v3 = acc[nt][3] + b1;
                v2 = v2 > 0.f ? v2 : 0.f;  v3 = v3 > 0.f ? v3 : 0.f;
                g_xh[(mrow0 + 8) * H1 + ncol]     = v2;
                g_xh[(mrow0 + 8) * H1 + ncol + 1] = v3;
                g_xhb[((mrow0 + 8) * H1 + ncol) >> 1] = __floats2bfloat162_rn(v2, v3);
            }
        }
    }
}

// ---------------------------------------------------------------------------
// Slotted CSR build — no scan, no cross-block sync.  Requires g_cur == 0 on
// entry (guaranteed: zero-init at load + gather re-zeroes every call).
__global__ void __launch_bounds__(1024) csr_kernel(const int* __restrict__ ei, int E) {
    __shared__ int hcnt [3000];
    __shared__ int hbase[3000];
    const int tid = threadIdx.x;
    const int CH = (E + gridDim.x - 1) / gridDim.x;
    const int lo = blockIdx.x * CH;
    const int hi = min(E, lo + CH);

    for (int i = tid; i < 3000; i += blockDim.x) hcnt[i] = 0;
    __syncthreads();
    for (int e = lo + tid; e < hi; e += blockDim.x)
        atomicAdd(&hcnt[ei[E + e]], 1);
    __syncthreads();
    for (int i = tid; i < 3000; i += blockDim.x) {
        int c = hcnt[i];
        if (c) hbase[i] = (i << 8) + atomicAdd(&g_cur[i], c);
        hcnt[i] = 0;
    }
    __syncthreads();
    for (int e = lo + tid; e < hi; e += blockDim.x) {
        int d = ei[E + e];
        int p = atomicAdd(&hcnt[d], 1);
        g_csr[hbase[d] + p] = ei[e];
    }
}

// ---------------------------------------------------------------------------
// Gather v4 (measured best): one 64-thread block per node; thread t owns
// features [4t,4t+4) = one 8B uint2 of bf16x2 per edge; smem-staged offsets;
// unroll 8; fp32 accumulation.  Epilogue resets g_cur for the next call.
__global__ void gather_kernel() {
    const int n = blockIdx.x;
    const int t = threadIdx.x;        // 0..63
    const int deg = g_cur[n];
    const int base = n << 8;

    __shared__ int soff[64];
    float4 acc = make_float4(0.f, 0.f, 0.f, 0.f);
    const uint2* __restrict__ xb = (const uint2*)g_xhb + t;   // row stride 64 uint2

    for (int j0 = 0; j0 < deg; j0 += 64) {
        int m = min(64, deg - j0);
        if (t < m) soff[t] = g_csr[base + j0 + t] << 6;       // row offset in uint2 units
        __syncthreads();
        int j = 0;
        for (; j + 8 <= m; j += 8) {
            uint2 v0 = xb[soff[j]];
            uint2 v1 = xb[soff[j + 1]];
            uint2 v2 = xb[soff[j + 2]];
            uint2 v3 = xb[soff[j + 3]];
            uint2 v4 = xb[soff[j + 4]];
            uint2 v5 = xb[soff[j + 5]];
            uint2 v6 = xb[soff[j + 6]];
            uint2 v7 = xb[soff[j + 7]];
#pragma unroll
            for (int u = 0; u < 8; u++) {
                uint2 v = (u == 0) ? v0 : (u == 1) ? v1 : (u == 2) ? v2 : (u == 3) ? v3
                        : (u == 4) ? v4 : (u == 5) ? v5 : (u == 6) ? v6 : v7;
                float2 f0 = __bfloat1622float2(*(const __nv_bfloat162*)&v.x);
                float2 f1 = __bfloat1622float2(*(const __nv_bfloat162*)&v.y);
                acc.x += f0.x; acc.y += f0.y; acc.z += f1.x; acc.w += f1.y;
            }
        }
        for (; j < m; j++) {
            uint2 v = xb[soff[j]];
            float2 f0 = __bfloat1622float2(*(const __nv_bfloat162*)&v.x);
            float2 f1 = __bfloat1622float2(*(const __nv_bfloat162*)&v.y);
            acc.x += f0.x; acc.y += f0.y; acc.z += f1.x; acc.w += f1.y;
        }
        __syncthreads();
    }
    float inv = 1.f / fmaxf((float)deg, 1.f);
    acc.x *= inv; acc.y *= inv; acc.z *= inv; acc.w *= inv;
    *(float4*)(g_agg + n * H1 + 4 * t) = acc;
    if (t == 0) g_cur[n] = 0;                  // reset for next invocation
}

// ---------------------------------------------------------------------------
// GEMM2 (tf32): only the 3 LIVE gates (i, c, o).  Packed 3000 x 384.
// 32x64x32 tile (2x grid of the 64-row version), double-buffered.
__global__ void gemm2_kernel(const float* __restrict__ Wrel,
                             const float* __restrict__ Wroot,
                             const float* __restrict__ bx,
                             const float* __restrict__ bh) {
    __shared__ unsigned As[2 * A_TILE];
    __shared__ unsigned Bs[2 * B_TILE];
    const int bm = blockIdx.y * 32;
    const int bn = blockIdx.x * 64;                 // packed col block (0..383)
    const int tid = threadIdx.x;
    const int warp = tid >> 5, lane = tid & 31;
    const int wm = warp >> 1, wn = warp & 1;
    const int gid = lane >> 2, tig = lane & 3;
    const int pg = bn >> 7;                         // packed gate 0..2
    const int wg = (pg == 0) ? 0 : pg + 1;          // actual gate 0,2,3
    const int obase = bn & 127;

    float acc[4][4];
#pragma unroll
    for (int nt = 0; nt < 4; nt++)
#pragma unroll
        for (int r = 0; r < 4; r++) acc[nt][r] = 0.f;

    const int r0 = tid >> 3;
    const int c8 = tid & 7;
    const int ob = tid & 63;
    const int kc = tid >> 6;     // 0..1

    float4 ra[2];
    float  rb[16];
#pragma unroll
    for (int rr = 0; rr < 2; rr++) {
        int gm = bm + r0 + rr * 16;
        ra[rr] = make_float4(0.f, 0.f, 0.f, 0.f);
        if (gm < N_PAD)
            ra[rr] = *(const float4*)(g_agg + (size_t)gm * H1 + 4 * c8);
    }
    {
        const float* Wb = Wrel + (size_t)wg * H1 * OUTD + obase;
#pragma unroll
        for (int i = 0; i < 16; i++)
            rb[i] = Wb[(size_t)(kc * 16 + i) * OUTD + ob];
    }

    for (int k0 = 0; k0 < 2 * H1; k0 += 32) {
        const int buf = (k0 >> 5) & 1;
        unsigned* Ab = As + buf * A_TILE;
        unsigned* Bb = Bs + buf * B_TILE;
#pragma unroll
        for (int rr = 0; rr < 2; rr++) {
            uint4 u = make_uint4(f2tf32(ra[rr].x), f2tf32(ra[rr].y),
                                 f2tf32(ra[rr].z), f2tf32(ra[rr].w));
            *(uint4*)&Ab[(r0 + rr * 16) * ASTRIDE + 4 * c8] = u;
        }
#pragma unroll
        for (int i = 0; i < 16; i++)
            Bb[(kc * 16 + i) * BSTRIDE + ob] = f2tf32(rb[i]);
        __syncthreads();
        if (k0 + 32 < 2 * H1) {
            int kn = k0 + 32;
            const float* Abase = (kn < H1) ? (g_agg + kn) : (g_xh + (kn - H1));
#pragma unroll
            for (int rr = 0; rr < 2; rr++) {
                int gm = bm + r0 + rr * 16;
                ra[rr] = make_float4(0.f, 0.f, 0.f, 0.f);
                if (gm < N_PAD)
                    ra[rr] = *(const float4*)(Abase + (size_t)gm * H1 + 4 * c8);
            }
            const float* Wb = (kn < H1)
                ? (Wrel  + (size_t)wg * H1 * OUTD + (size_t)kn * OUTD + obase)
                : (Wroot + (size_t)wg * H1 * OUTD + (size_t)(kn - H1) * OUTD + obase);
#pragma unroll
            for (int i = 0; i < 16; i++)
                rb[i] = Wb[(size_t)(kc * 16 + i) * OUTD + ob];
        }

#pragma unroll
        for (int ks = 0; ks < 4; ks++) {
            int kk = ks * 8;
            unsigned a[4], b[4][2];
            const int ar = wm * 16;
            a[0] = Ab[(ar + gid) * ASTRIDE + kk + tig];
            a[1] = Ab[(ar + gid + 8) * ASTRIDE + kk + tig];
            a[2] = Ab[(ar + gid) * ASTRIDE + kk + tig + 4];
            a[3] = Ab[(ar + gid + 8) * ASTRIDE + kk + tig + 4];
#pragma unroll
            for (int nt = 0; nt < 4; nt++) {
                int nc = wn * 32 + nt * 8 + gid;
                b[nt][0] = Bb[(kk + tig) * BSTRIDE + nc];
                b[nt][1] = Bb[(kk + tig + 4) * BSTRIDE + nc];
            }
#pragma unroll
            for (int nt = 0; nt < 4; nt++)
                mma_tf32(acc[nt], a, b[nt]);
        }
        __syncthreads();
    }

    {
        int mrow0 = bm + wm * 16 + gid;
#pragma unroll
        for (int nt = 0; nt < 4; nt++) {
            int ncol = bn + wn * 32 + nt * 8 + 2 * tig;      // packed col
            int wcol0 = wg * OUTD + (ncol & 127);            // weight-space col
            float b0 = bx[wcol0] + bh[wcol0];
            float b1 = bx[wcol0 + 1] + bh[wcol0 + 1];
            if (mrow0 < N_PAD) {
                g_gate[(size_t)mrow0 * GATES_N + ncol]     = acc[nt][0] + b0;
                g_gate[(size_t)mrow0 * GATES_N + ncol + 1] = acc[nt][1] + b1;
            }
            if (mrow0 + 8 < N_PAD) {
                g_gate[(size_t)(mrow0 + 8) * GATES_N + ncol]     = acc[nt][2] + b0;
                g_gate[(size_t)(mrow0 + 8) * GATES_N + ncol + 1] = acc[nt][3] + b1;
            }
        }
    }
}

// ---------------------------------------------------------------------------
// Gates + H + final projection.  Packed gates: [i | c | o] stride 384.
__global__ void finish_kernel(const float* __restrict__ fcw,
                              const float* __restrict__ fcb,
                              float* __restrict__ out,
                              float* __restrict__ Hout) {
    int n = blockIdx.x;       // 0..2999
    int o = threadIdx.x;      // 0..127
    const float* g = g_gate + (size_t)n * GATES_N;
    float gi = g[o];
    float gc = g[OUTD + o];
    float go = g[2 * OUTD + o];
    float I = 1.f / (1.f + __expf(-gi));
    float T = tanhf(gc);
    float O = 1.f / (1.f + __expf(-go));
    float C = I * T;
    float H = O * tanhf(C);
    Hout[n * OUTD + o] = H;

    float v = H * fcw[o];
#pragma unroll
    for (int s = 16; s > 0; s >>= 1)
        v += __shfl_down_sync(0xffffffffu, v, s);
    __shared__ float sred[4];
    if ((o & 31) == 0) sred[o >> 5] = v;
    __syncthreads();
    if (o == 0 && n < N_REAL)
        out[n] = sred[0] + sred[1] + sred[2] + sred[3] + fcb[0];
}

// ---------------------------------------------------------------------------
extern "C" void kernel_launch(void* const* d_in, const int* in_sizes, int n_in,
                              void* d_out, int out_size) {
    const float* x      = (const float*)d_in[0];
    const int*   ei     = (const int*)  d_in[1];
    const float* fc0_w  = (const float*)d_in[2];
    const float* fc0_b  = (const float*)d_in[3];
    const float* Wx_rel = (const float*)d_in[4];
    const float* Wx_root= (const float*)d_in[5];
    const float* bx     = (const float*)d_in[6];
    // d_in[7] Wh_rel, d_in[8] Wh_root: multiplied by zero state -> unused
    const float* bh     = (const float*)d_in[9];
    const float* fc_w   = (const float*)d_in[10];
    const float* fc_b   = (const float*)d_in[11];
    const int E = in_sizes[1] / 2;

    float* out  = (float*)d_out;          // [2500]
    float* Hout = out + N_REAL;           // [3000 x 128]

    csr_kernel<<<CSR_BLOCKS, 1024>>>(ei, E);

    dim3 g1(H1 / 64, (N_PAD + 31) / 32);           // 4 x 94 (covers pad rows)
    gemm1_kernel<<<g1, 128>>>(x, fc0_w, fc0_b);

    gather_kernel<<<N_PAD, 64>>>();

    dim3 g2(GATES_N / 64, (N_PAD + 31) / 32);      // 6 x 94
    gemm2_kernel<<<g2, 128>>>(Wx_rel, Wx_root, bx, bh);

    finish_kernel<<<N_PAD, OUTD>>>(fc_w, fc_b, out, Hout);
}

// round 16
// speedup vs baseline: 1.1694x; 1.1694x over previous
#include <cuda_runtime.h>
#include <cuda_bf16.h>

#define N_PAD   3000
#define N_REAL  2500
#define F_IN    1024
#define H1      256
#define OUTD    128
#define GATES_N 384   // 3 live gates (i, c, o) x 128 — forget gate dead (C_prev=0)
#define SLOT    256   // per-node CSR capacity (max degree ~137, 15-sigma safe)
#define CSR_BLOCKS 128

// Scratch (device globals — no allocation allowed).  g_cur is zero-initialized
// at module load; gather_kernel re-zeroes it at the end of every call.
__device__ float           g_xh  [N_PAD * H1];        // relu(fc0(x_pad)) fp32 (GEMM2 operand)
__device__ __nv_bfloat162  g_xhb [N_PAD * H1 / 2];    // same, bf16 (gather operand)
__device__ float           g_agg [N_PAD * H1];        // mean-aggregated neighbors
__device__ float           g_gate[N_PAD * GATES_N];   // pre-activation gates (i,c,o packed)
__device__ int             g_cur [N_PAD];             // per-node fill cursor == degree
__device__ int             g_csr [N_PAD * SLOT];      // slotted CSR (stride 256 per node)

// ---------------------------------------------------------------------------
__device__ __forceinline__ unsigned f2tf32(float f) {
    unsigned u;
    asm("cvt.rna.tf32.f32 %0, %1;" : "=r"(u) : "f"(f));
    return u;
}

__device__ __forceinline__ uint4 cvt4(float4 v) {
    return make_uint4(f2tf32(v.x), f2tf32(v.y), f2tf32(v.z), f2tf32(v.w));
}

__device__ __forceinline__ void mma_tf32(float* c, const unsigned* a, const unsigned* b) {
    asm volatile(
        "mma.sync.aligned.m16n8k8.row.col.f32.tf32.tf32.f32 "
        "{%0,%1,%2,%3}, {%4,%5,%6,%7}, {%8,%9}, {%0,%1,%2,%3};\n"
        : "+f"(c[0]), "+f"(c[1]), "+f"(c[2]), "+f"(c[3])
        : "r"(a[0]), "r"(a[1]), "r"(a[2]), "r"(a[3]), "r"(b[0]), "r"(b[1]));
}

// ---------------------------------------------------------------------------
// Smem strides (conflict-free fragment loads):
//  A  [m][k] stride 40: bank(40m+k) = 8m+k mod 32, distinct for m0..7 x k0..3
//  B1 [n][k] stride 36: bank(36n+k) = 4n+k mod 32, distinct for n(gid)0..7 x k0..3
//  B2 [k][n] stride 72: bank(72k+n) = 8k+n mod 32, distinct for k0..3 x n0..7
#define ASTRIDE  40
#define BSTRIDE1 36
#define BSTRIDE2 72
#define A_TILE   (64 * ASTRIDE)
#define B_TILE1  (64 * BSTRIDE1)
#define B_TILE2  (32 * BSTRIDE2)

// GEMM1: xh[m,n] = relu(sum_k x[m,k]*w[n,k] + b[n]) for m<2500; padded rows
// 2500..2999 have zero A so the result is exactly relu(b[n]) — grid covers
// 3008 rows, no separate init kernel.  64x64x32 tile, 128 threads (4 warps,
// 32x32 warp tiles), double-buffered, register prefetch during MMA.
// B smem is [n][k] so the k-contiguous float4 loads store as STS.128.
__global__ void gemm1_kernel(const float* __restrict__ x,
                             const float* __restrict__ w,
                             const float* __restrict__ bias) {
    __shared__ unsigned As[2 * A_TILE];
    __shared__ unsigned Bs[2 * B_TILE1];
    const int bm = blockIdx.y * 64;
    const int bn = blockIdx.x * 64;
    const int tid = threadIdx.x;
    const int warp = tid >> 5, lane = tid & 31;
    const int wm = warp >> 1, wn = warp & 1;
    const int gid = lane >> 2, tig = lane & 3;

    float acc[2][4][4];
#pragma unroll
    for (int mt = 0; mt < 2; mt++)
#pragma unroll
        for (int nt = 0; nt < 4; nt++)
#pragma unroll
            for (int r = 0; r < 4; r++) acc[mt][nt][r] = 0.f;

    const int r0 = tid >> 3;        // 0..15
    const int c8 = tid & 7;         // 0..7 (float4-column of A)
    const int nb = tid & 63;        // 0..63 (B row = output col)
    const int cb = tid >> 6;        // 0..1

    float4 ra[4], rb[4];
#pragma unroll
    for (int rr = 0; rr < 4; rr++) {
        int gm = bm + r0 + rr * 16;
        ra[rr] = make_float4(0.f, 0.f, 0.f, 0.f);
        if (gm < N_REAL)
            ra[rr] = *(const float4*)(x + (size_t)gm * F_IN + 4 * c8);
    }
#pragma unroll
    for (int i = 0; i < 4; i++)
        rb[i] = *(const float4*)(w + (size_t)(bn + nb) * F_IN + 4 * (cb * 4 + i));

    for (int k0 = 0; k0 < F_IN; k0 += 32) {
        const int buf = (k0 >> 5) & 1;
        unsigned* Ab = As + buf * A_TILE;
        unsigned* Bb = Bs + buf * B_TILE1;
#pragma unroll
        for (int rr = 0; rr < 4; rr++)
            *(uint4*)&Ab[(r0 + rr * 16) * ASTRIDE + 4 * c8] = cvt4(ra[rr]);
#pragma unroll
        for (int i = 0; i < 4; i++) {
            int c = cb * 4 + i;                       // k-chunk 0..7
            *(uint4*)&Bb[nb * BSTRIDE1 + 4 * c] = cvt4(rb[i]);
        }
        __syncthreads();
        if (k0 + 32 < F_IN) {
            int kn = k0 + 32;
#pragma unroll
            for (int rr = 0; rr < 4; rr++) {
                int gm = bm + r0 + rr * 16;
                ra[rr] = make_float4(0.f, 0.f, 0.f, 0.f);
                if (gm < N_REAL)
                    ra[rr] = *(const float4*)(x + (size_t)gm * F_IN + kn + 4 * c8);
            }
#pragma unroll
            for (int i = 0; i < 4; i++)
                rb[i] = *(const float4*)(w + (size_t)(bn + nb) * F_IN + kn + 4 * (cb * 4 + i));
        }

#pragma unroll
        for (int ks = 0; ks < 4; ks++) {
            int kk = ks * 8;
            unsigned a[2][4], b[4][2];
#pragma unroll
            for (int mt = 0; mt < 2; mt++) {
                int ar = wm * 32 + mt * 16;
                a[mt][0] = Ab[(ar + gid) * ASTRIDE + kk + tig];
                a[mt][1] = Ab[(ar + gid + 8) * ASTRIDE + kk + tig];
                a[mt][2] = Ab[(ar + gid) * ASTRIDE + kk + tig + 4];
                a[mt][3] = Ab[(ar + gid + 8) * ASTRIDE + kk + tig + 4];
            }
#pragma unroll
            for (int nt = 0; nt < 4; nt++) {
                int nc = wn * 32 + nt * 8 + gid;
                b[nt][0] = Bb[nc * BSTRIDE1 + kk + tig];
                b[nt][1] = Bb[nc * BSTRIDE1 + kk + tig + 4];
            }
#pragma unroll
            for (int mt = 0; mt < 2; mt++)
#pragma unroll
                for (int nt = 0; nt < 4; nt++)
                    mma_tf32(acc[mt][nt], a[mt], b[nt]);
        }
    }

#pragma unroll
    for (int mt = 0; mt < 2; mt++) {
        int mrow0 = bm + wm * 32 + mt * 16 + gid;
#pragma unroll
        for (int nt = 0; nt < 4; nt++) {
            int ncol = bn + wn * 32 + nt * 8 + 2 * tig;     // even
            float b0 = bias[ncol], b1 = bias[ncol + 1];
            if (mrow0 < N_PAD) {
                float v0 = acc[mt][nt][0] + b0, v1 = acc[mt][nt][1] + b1;
                v0 = v0 > 0.f ? v0 : 0.f;  v1 = v1 > 0.f ? v1 : 0.f;
                g_xh[mrow0 * H1 + ncol]     = v0;
                g_xh[mrow0 * H1 + ncol + 1] = v1;
                g_xhb[(mrow0 * H1 + ncol) >> 1] = __floats2bfloat162_rn(v0, v1);
            }
            if (mrow0 + 8 < N_PAD) {
                float v2 = acc[mt][nt][2] + b0, v3 = acc[mt][nt][3] + b1;
                v2 = v2 > 0.f ? v2 : 0.f;  v3 = v3 > 0.f ? v3 : 0.f;
                g_xh[(mrow0 + 8) * H1 + ncol]     = v2;
                g_xh[(mrow0 + 8) * H1 + ncol + 1] = v3;
                g_xhb[((mrow0 + 8) * H1 + ncol) >> 1] = __floats2bfloat162_rn(v2, v3);
            }
        }
    }
}

// ---------------------------------------------------------------------------
// Slotted CSR build — no scan, no cross-block sync.  Requires g_cur == 0 on
// entry (zero-init at load + gather re-zeroes every call).
__global__ void __launch_bounds__(1024) csr_kernel(const int* __restrict__ ei, int E) {
    __shared__ int hcnt [3000];
    __shared__ int hbase[3000];
    const int tid = threadIdx.x;
    const int CH = (E + gridDim.x - 1) / gridDim.x;
    const int lo = blockIdx.x * CH;
    const int hi = min(E, lo + CH);

    for (int i = tid; i < 3000; i += blockDim.x) hcnt[i] = 0;
    __syncthreads();
    for (int e = lo + tid; e < hi; e += blockDim.x)
        atomicAdd(&hcnt[ei[E + e]], 1);
    __syncthreads();
    for (int i = tid; i < 3000; i += blockDim.x) {
        int c = hcnt[i];
        if (c) hbase[i] = (i << 8) + atomicAdd(&g_cur[i], c);
        hcnt[i] = 0;
    }
    __syncthreads();
    for (int e = lo + tid; e < hi; e += blockDim.x) {
        int d = ei[E + e];
        int p = atomicAdd(&hcnt[d], 1);
        g_csr[hbase[d] + p] = ei[e];
    }
}

// ---------------------------------------------------------------------------
// Gather v4 (measured best): one 64-thread block per node; thread t owns
// features [4t,4t+4) = one 8B uint2 of bf16x2 per edge; smem-staged offsets;
// unroll 8; fp32 accumulation.  Epilogue resets g_cur for the next call.
__global__ void gather_kernel() {
    const int n = blockIdx.x;
    const int t = threadIdx.x;        // 0..63
    const int deg = g_cur[n];
    const int base = n << 8;

    __shared__ int soff[64];
    float4 acc = make_float4(0.f, 0.f, 0.f, 0.f);
    const uint2* __restrict__ xb = (const uint2*)g_xhb + t;   // row stride 64 uint2

    for (int j0 = 0; j0 < deg; j0 += 64) {
        int m = min(64, deg - j0);
        if (t < m) soff[t] = g_csr[base + j0 + t] << 6;       // row offset in uint2 units
        __syncthreads();
        int j = 0;
        for (; j + 8 <= m; j += 8) {
            uint2 v0 = xb[soff[j]];
            uint2 v1 = xb[soff[j + 1]];
            uint2 v2 = xb[soff[j + 2]];
            uint2 v3 = xb[soff[j + 3]];
            uint2 v4 = xb[soff[j + 4]];
            uint2 v5 = xb[soff[j + 5]];
            uint2 v6 = xb[soff[j + 6]];
            uint2 v7 = xb[soff[j + 7]];
#pragma unroll
            for (int u = 0; u < 8; u++) {
                uint2 v = (u == 0) ? v0 : (u == 1) ? v1 : (u == 2) ? v2 : (u == 3) ? v3
                        : (u == 4) ? v4 : (u == 5) ? v5 : (u == 6) ? v6 : v7;
                float2 f0 = __bfloat1622float2(*(const __nv_bfloat162*)&v.x);
                float2 f1 = __bfloat1622float2(*(const __nv_bfloat162*)&v.y);
                acc.x += f0.x; acc.y += f0.y; acc.z += f1.x; acc.w += f1.y;
            }
        }
        for (; j < m; j++) {
            uint2 v = xb[soff[j]];
            float2 f0 = __bfloat1622float2(*(const __nv_bfloat162*)&v.x);
            float2 f1 = __bfloat1622float2(*(const __nv_bfloat162*)&v.y);
            acc.x += f0.x; acc.y += f0.y; acc.z += f1.x; acc.w += f1.y;
        }
        __syncthreads();
    }
    float inv = 1.f / fmaxf((float)deg, 1.f);
    acc.x *= inv; acc.y *= inv; acc.z *= inv; acc.w *= inv;
    *(float4*)(g_agg + n * H1 + 4 * t) = acc;
    if (t == 0) g_cur[n] = 0;                  // reset for next invocation
}

// ---------------------------------------------------------------------------
// GEMM2 (tf32): only the 3 LIVE gates (i, c, o).  Packed 3000 x 384.
// 64x64x32 tile, double-buffered.  B staged with float4 LDG along the
// contiguous o-dim + STS.128 into the [k][n] smem layout (no transpose).
__global__ void gemm2_kernel(const float* __restrict__ Wrel,
                             const float* __restrict__ Wroot,
                             const float* __restrict__ bx,
                             const float* __restrict__ bh) {
    __shared__ unsigned As[2 * A_TILE];
    __shared__ unsigned Bs[2 * B_TILE2];
    const int bm = blockIdx.y * 64;
    const int bn = blockIdx.x * 64;                 // packed col block (0..383)
    const int tid = threadIdx.x;
    const int warp = tid >> 5, lane = tid & 31;
    const int wm = warp >> 1, wn = warp & 1;
    const int gid = lane >> 2, tig = lane & 3;
    const int pg = bn >> 7;                         // packed gate 0..2
    const int wg = (pg == 0) ? 0 : pg + 1;          // actual gate 0,2,3
    const int obase = bn & 127;

    float acc[2][4][4];
#pragma unroll
    for (int mt = 0; mt < 2; mt++)
#pragma unroll
        for (int nt = 0; nt < 4; nt++)
#pragma unroll
            for (int r = 0; r < 4; r++) acc[mt][nt][r] = 0.f;

    const int r0 = tid >> 3;        // 0..15 (A row group)
    const int c8 = tid & 7;         // 0..7  (A float4-col)
    const int trow  = tid >> 4;     // 0..7  (B k-row group)
    const int tcol4 = (tid & 15) * 4; // 0..60 (B float4-col)

    float4 ra[4], rbv[4];
#pragma unroll
    for (int rr = 0; rr < 4; rr++) {
        int gm = bm + r0 + rr * 16;
        ra[rr] = make_float4(0.f, 0.f, 0.f, 0.f);
        if (gm < N_PAD)
            ra[rr] = *(const float4*)(g_agg + (size_t)gm * H1 + 4 * c8);
    }
    {
        const float* Wb = Wrel + (size_t)wg * H1 * OUTD + obase;
#pragma unroll
        for (int j = 0; j < 4; j++)
            rbv[j] = *(const float4*)(Wb + (size_t)(trow + j * 8) * OUTD + tcol4);
    }

    for (int k0 = 0; k0 < 2 * H1; k0 += 32) {
        const int buf = (k0 >> 5) & 1;
        unsigned* Ab = As + buf * A_TILE;
        unsigned* Bb = Bs + buf * B_TILE2;
#pragma unroll
        for (int rr = 0; rr < 4; rr++)
            *(uint4*)&Ab[(r0 + rr * 16) * ASTRIDE + 4 * c8] = cvt4(ra[rr]);
#pragma unroll
        for (int j = 0; j < 4; j++)
            *(uint4*)&Bb[(trow + j * 8) * BSTRIDE2 + tcol4] = cvt4(rbv[j]);
        __syncthreads();
        if (k0 + 32 < 2 * H1) {
            int kn = k0 + 32;
            const float* Abase = (kn < H1) ? (g_agg + kn) : (g_xh + (kn - H1));
#pragma unroll
            for (int rr = 0; rr < 4; rr++) {
                int gm = bm + r0 + rr * 16;
                ra[rr] = make_float4(0.f, 0.f, 0.f, 0.f);
                if (gm < N_PAD)
                    ra[rr] = *(const float4*)(Abase + (size_t)gm * H1 + 4 * c8);
            }
            const float* Wb = (kn < H1)
                ? (Wrel  + (size_t)wg * H1 * OUTD + (size_t)kn * OUTD + obase)
                : (Wroot + (size_t)wg * H1 * OUTD + (size_t)(kn - H1) * OUTD + obase);
#pragma unroll
            for (int j = 0; j < 4; j++)
                rbv[j] = *(const float4*)(Wb + (size_t)(trow + j * 8) * OUTD + tcol4);
        }

#pragma unroll
        for (int ks = 0; ks < 4; ks++) {
            int kk = ks * 8;
            unsigned a[2][4], b[4][2];
#pragma unroll
            for (int mt = 0; mt < 2; mt++) {
                int ar = wm * 32 + mt * 16;
                a[mt][0] = Ab[(ar + gid) * ASTRIDE + kk + tig];
                a[mt][1] = Ab[(ar + gid + 8) * ASTRIDE + kk + tig];
                a[mt][2] = Ab[(ar + gid) * ASTRIDE + kk + tig + 4];
                a[mt][3] = Ab[(ar + gid + 8) * ASTRIDE + kk + tig + 4];
            }
#pragma unroll
            for (int nt = 0; nt < 4; nt++) {
                int nc = wn * 32 + nt * 8 + gid;
                b[nt][0] = Bb[(kk + tig) * BSTRIDE2 + nc];
                b[nt][1] = Bb[(kk + tig + 4) * BSTRIDE2 + nc];
            }
#pragma unroll
            for (int mt = 0; mt < 2; mt++)
#pragma unroll
                for (int nt = 0; nt < 4; nt++)
                    mma_tf32(acc[mt][nt], a[mt], b[nt]);
        }
    }

#pragma unroll
    for (int mt = 0; mt < 2; mt++) {
        int mrow0 = bm + wm * 32 + mt * 16 + gid;
#pragma unroll
        for (int nt = 0; nt < 4; nt++) {
            int ncol = bn + wn * 32 + nt * 8 + 2 * tig;      // packed col
            int wcol0 = wg * OUTD + (ncol & 127);            // weight-space col
            float b0 = bx[wcol0] + bh[wcol0];
            float b1 = bx[wcol0 + 1] + bh[wcol0 + 1];
            if (mrow0 < N_PAD) {
                g_gate[(size_t)mrow0 * GATES_N + ncol]     = acc[mt][nt][0] + b0;
                g_gate[(size_t)mrow0 * GATES_N + ncol + 1] = acc[mt][nt][1] + b1;
            }
            if (mrow0 + 8 < N_PAD) {
                g_gate[(size_t)(mrow0 + 8) * GATES_N + ncol]     = acc[mt][nt][2] + b0;
                g_gate[(size_t)(mrow0 + 8) * GATES_N + ncol + 1] = acc[mt][nt][3] + b1;
            }
        }
    }
}

// ---------------------------------------------------------------------------
// Gates + H + final projection.  Packed gates: [i | c | o] stride 384.
__global__ void finish_kernel(const float* __restrict__ fcw,
                              const float* __restrict__ fcb,
                              float* __restrict__ out,
                              float* __restrict__ Hout) {
    int n = blockIdx.x;       // 0..2999
    int o = threadIdx.x;      // 0..127
    const float* g = g_gate + (size_t)n * GATES_N;
    float gi = g[o];
    float gc = g[OUTD + o];
    float go = g[2 * OUTD + o];
    float I = 1.f / (1.f + __expf(-gi));
    float T = tanhf(gc);
    float O = 1.f / (1.f + __expf(-go));
    float C = I * T;
    float H = O * tanhf(C);
    Hout[n * OUTD + o] = H;

    float v = H * fcw[o];
#pragma unroll
    for (int s = 16; s > 0; s >>= 1)
        v += __shfl_down_sync(0xffffffffu, v, s);
    __shared__ float sred[4];
    if ((o & 31) == 0) sred[o >> 5] = v;
    __syncthreads();
    if (o == 0 && n < N_REAL)
        out[n] = sred[0] + sred[1] + sred[2] + sred[3] + fcb[0];
}

// ---------------------------------------------------------------------------
extern "C" void kernel_launch(void* const* d_in, const int* in_sizes, int n_in,
                              void* d_out, int out_size) {
    const float* x      = (const float*)d_in[0];
    const int*   ei     = (const int*)  d_in[1];
    const float* fc0_w  = (const float*)d_in[2];
    const float* fc0_b  = (const float*)d_in[3];
    const float* Wx_rel = (const float*)d_in[4];
    const float* Wx_root= (const float*)d_in[5];
    const float* bx     = (const float*)d_in[6];
    // d_in[7] Wh_rel, d_in[8] Wh_root: multiplied by zero state -> unused
    const float* bh     = (const float*)d_in[9];
    const float* fc_w   = (const float*)d_in[10];
    const float* fc_b   = (const float*)d_in[11];
    const int E = in_sizes[1] / 2;

    float* out  = (float*)d_out;          // [2500]
    float* Hout = out + N_REAL;           // [3000 x 128]

    csr_kernel<<<CSR_BLOCKS, 1024>>>(ei, E);

    dim3 g1(H1 / 64, (N_PAD + 63) / 64);           // 4 x 47 (covers pad rows)
    gemm1_kernel<<<g1, 128>>>(x, fc0_w, fc0_b);

    gather_kernel<<<N_PAD, 64>>>();

    dim3 g2(GATES_N / 64, (N_PAD + 63) / 64);      // 6 x 47
    gemm2_kernel<<<g2, 128>>>(Wx_rel, Wx_root, bx, bh);

    finish_kernel<<<N_PAD, OUTD>>>(fc_w, fc_b, out, Hout);
}

// round 17
// speedup vs baseline: 1.2416x; 1.0617x over previous
#include <cuda_runtime.h>
#include <cuda_bf16.h>

#define N_PAD   3000
#define N_REAL  2500
#define F_IN    1024
#define H1      256
#define OUTD    128
#define GATES_N 384   // 3 live gates (i, c, o) x 128 — forget gate dead (C_prev=0)
#define SLOT    256   // per-node CSR capacity (max degree ~137, 15-sigma safe)
#define CSR_BLOCKS 128
#define G1_TILES  (4 * 47)     // gemm1 grid: 4 n-tiles x 47 m-tiles

// Scratch (device globals — no allocation allowed).  g_cur is zero-initialized
// at module load; gather_kernel re-zeroes it at the end of every call.
__device__ float           g_xh  [N_PAD * H1];        // relu(fc0(x_pad)) fp32 (GEMM2 operand)
__device__ __nv_bfloat162  g_xhb [N_PAD * H1 / 2];    // same, bf16 (gather operand)
__device__ float           g_agg [N_PAD * H1];        // mean-aggregated neighbors
__device__ float           g_gate[N_PAD * GATES_N];   // pre-activation gates (i,c,o packed)
__device__ int             g_cur [N_PAD];             // per-node fill cursor == degree
__device__ int             g_csr [N_PAD * SLOT];      // slotted CSR (stride 256 per node)

// ---------------------------------------------------------------------------
__device__ __forceinline__ unsigned f2tf32(float f) {
    unsigned u;
    asm("cvt.rna.tf32.f32 %0, %1;" : "=r"(u) : "f"(f));
    return u;
}

__device__ __forceinline__ uint4 cvt4(float4 v) {
    return make_uint4(f2tf32(v.x), f2tf32(v.y), f2tf32(v.z), f2tf32(v.w));
}

__device__ __forceinline__ void mma_tf32(float* c, const unsigned* a, const unsigned* b) {
    asm volatile(
        "mma.sync.aligned.m16n8k8.row.col.f32.tf32.tf32.f32 "
        "{%0,%1,%2,%3}, {%4,%5,%6,%7}, {%8,%9}, {%0,%1,%2,%3};\n"
        : "+f"(c[0]), "+f"(c[1]), "+f"(c[2]), "+f"(c[3])
        : "r"(a[0]), "r"(a[1]), "r"(a[2]), "r"(a[3]), "r"(b[0]), "r"(b[1]));
}

// ---------------------------------------------------------------------------
// Smem strides (conflict-free fragment loads):
//  A  [m][k] stride 40: bank(40m+k) = 8m+k mod 32, distinct for m0..7 x k0..3
//  B1 [n][k] stride 36: bank(36n+k) = 4n+k mod 32, distinct for n(gid)0..7 x k0..3
//  B2 [k][n] stride 72: bank(72k+n) = 8k+n mod 32, distinct for k0..3 x n0..7
#define ASTRIDE  40
#define BSTRIDE1 36
#define BSTRIDE2 72
#define A_TILE   (64 * ASTRIDE)
#define B_TILE1  (64 * BSTRIDE1)
#define B_TILE2  (32 * BSTRIDE2)
// merged-kernel smem overlay: gemm1 needs 2*(A_TILE+B_TILE1)=9728 words,
// csr needs 6000 words; take the max.
#define MERGED_SMEM_WORDS (2 * (A_TILE + B_TILE1))

// ---------------------------------------------------------------------------
// Merged kernel: blocks [0, CSR_BLOCKS) build the slotted CSR (needs only the
// edge list); blocks [CSR_BLOCKS, CSR_BLOCKS+G1_TILES) run GEMM1 tiles (needs
// only x/W/bias).  The two jobs are data-independent, so fusing them into one
// launch overlaps them without streams and drops a launch boundary.
__global__ void __launch_bounds__(128) csr_gemm1_kernel(
    const float* __restrict__ x,
    const float* __restrict__ w,
    const float* __restrict__ bias,
    const int*   __restrict__ ei, int E) {
    __shared__ unsigned smem_raw[MERGED_SMEM_WORDS];
    const int tid = threadIdx.x;

    if (blockIdx.x < CSR_BLOCKS) {
        // ---------------- CSR build (128 threads) ----------------
        int* hcnt  = (int*)smem_raw;          // [3000]
        int* hbase = (int*)smem_raw + 3000;   // [3000]
        const int CH = (E + CSR_BLOCKS - 1) / CSR_BLOCKS;
        const int lo = blockIdx.x * CH;
        const int hi = min(E, lo + CH);

        for (int i = tid; i < 3000; i += 128) hcnt[i] = 0;
        __syncthreads();
        for (int e = lo + tid; e < hi; e += 128)
            atomicAdd(&hcnt[ei[E + e]], 1);
        __syncthreads();
        for (int i = tid; i < 3000; i += 128) {
            int c = hcnt[i];
            if (c) hbase[i] = (i << 8) + atomicAdd(&g_cur[i], c);
            hcnt[i] = 0;
        }
        __syncthreads();
        for (int e = lo + tid; e < hi; e += 128) {
            int d = ei[E + e];
            int p = atomicAdd(&hcnt[d], 1);
            g_csr[hbase[d] + p] = ei[e];
        }
        return;
    }

    // ---------------- GEMM1 tile (64x64x32, tf32, double-buffered) ----------
    // xh[m,n] = relu(sum_k x[m,k]*w[n,k] + b[n]); pad rows get relu(b[n]).
    const int tb = blockIdx.x - CSR_BLOCKS;
    const int bm = (tb >> 2) * 64;            // 0..46 -> covers 3008 rows
    const int bn = (tb & 3) * 64;
    unsigned* As = smem_raw;                  // 2 * A_TILE
    unsigned* Bs = smem_raw + 2 * A_TILE;     // 2 * B_TILE1
    const int warp = tid >> 5, lane = tid & 31;
    const int wm = warp >> 1, wn = warp & 1;
    const int gid = lane >> 2, tig = lane & 3;

    float acc[2][4][4];
#pragma unroll
    for (int mt = 0; mt < 2; mt++)
#pragma unroll
        for (int nt = 0; nt < 4; nt++)
#pragma unroll
            for (int r = 0; r < 4; r++) acc[mt][nt][r] = 0.f;

    const int r0 = tid >> 3;        // 0..15
    const int c8 = tid & 7;         // 0..7 (float4-column of A)
    const int nb = tid & 63;        // 0..63 (B row = output col)
    const int cb = tid >> 6;        // 0..1

    float4 ra[4], rb[4];
#pragma unroll
    for (int rr = 0; rr < 4; rr++) {
        int gm = bm + r0 + rr * 16;
        ra[rr] = make_float4(0.f, 0.f, 0.f, 0.f);
        if (gm < N_REAL)
            ra[rr] = *(const float4*)(x + (size_t)gm * F_IN + 4 * c8);
    }
#pragma unroll
    for (int i = 0; i < 4; i++)
        rb[i] = *(const float4*)(w + (size_t)(bn + nb) * F_IN + 4 * (cb * 4 + i));

    for (int k0 = 0; k0 < F_IN; k0 += 32) {
        const int buf = (k0 >> 5) & 1;
        unsigned* Ab = As + buf * A_TILE;
        unsigned* Bb = Bs + buf * B_TILE1;
#pragma unroll
        for (int rr = 0; rr < 4; rr++)
            *(uint4*)&Ab[(r0 + rr * 16) * ASTRIDE + 4 * c8] = cvt4(ra[rr]);
#pragma unroll
        for (int i = 0; i < 4; i++) {
            int c = cb * 4 + i;                       // k-chunk 0..7
            *(uint4*)&Bb[nb * BSTRIDE1 + 4 * c] = cvt4(rb[i]);
        }
        __syncthreads();
        if (k0 + 32 < F_IN) {
            int kn = k0 + 32;
#pragma unroll
            for (int rr = 0; rr < 4; rr++) {
                int gm = bm + r0 + rr * 16;
                ra[rr] = make_float4(0.f, 0.f, 0.f, 0.f);
                if (gm < N_REAL)
                    ra[rr] = *(const float4*)(x + (size_t)gm * F_IN + kn + 4 * c8);
            }
#pragma unroll
            for (int i = 0; i < 4; i++)
                rb[i] = *(const float4*)(w + (size_t)(bn + nb) * F_IN + kn + 4 * (cb * 4 + i));
        }

#pragma unroll
        for (int ks = 0; ks < 4; ks++) {
            int kk = ks * 8;
            unsigned a[2][4], b[4][2];
#pragma unroll
            for (int mt = 0; mt < 2; mt++) {
                int ar = wm * 32 + mt * 16;
                a[mt][0] = Ab[(ar + gid) * ASTRIDE + kk + tig];
                a[mt][1] = Ab[(ar + gid + 8) * ASTRIDE + kk + tig];
                a[mt][2] = Ab[(ar + gid) * ASTRIDE + kk + tig + 4];
                a[mt][3] = Ab[(ar + gid + 8) * ASTRIDE + kk + tig + 4];
            }
#pragma unroll
            for (int nt = 0; nt < 4; nt++) {
                int nc = wn * 32 + nt * 8 + gid;
                b[nt][0] = Bb[nc * BSTRIDE1 + kk + tig];
                b[nt][1] = Bb[nc * BSTRIDE1 + kk + tig + 4];
            }
#pragma unroll
            for (int mt = 0; mt < 2; mt++)
#pragma unroll
                for (int nt = 0; nt < 4; nt++)
                    mma_tf32(acc[mt][nt], a[mt], b[nt]);
        }
    }

#pragma unroll
    for (int mt = 0; mt < 2; mt++) {
        int mrow0 = bm + wm * 32 + mt * 16 + gid;
#pragma unroll
        for (int nt = 0; nt < 4; nt++) {
            int ncol = bn + wn * 32 + nt * 8 + 2 * tig;     // even
            float b0 = bias[ncol], b1 = bias[ncol + 1];
            if (mrow0 < N_PAD) {
                float v0 = acc[mt][nt][0] + b0, v1 = acc[mt][nt][1] + b1;
                v0 = v0 > 0.f ? v0 : 0.f;  v1 = v1 > 0.f ? v1 : 0.f;
                g_xh[mrow0 * H1 + ncol]     = v0;
                g_xh[mrow0 * H1 + ncol + 1] = v1;
                g_xhb[(mrow0 * H1 + ncol) >> 1] = __floats2bfloat162_rn(v0, v1);
            }
            if (mrow0 + 8 < N_PAD) {
                float v2 = acc[mt][nt][2] + b0, v3 = acc[mt][nt][3] + b1;
                v2 = v2 > 0.f ? v2 : 0.f;  v3 = v3 > 0.f ? v3 : 0.f;
                g_xh[(mrow0 + 8) * H1 + ncol]     = v2;
                g_xh[(mrow0 + 8) * H1 + ncol + 1] = v3;
                g_xhb[((mrow0 + 8) * H1 + ncol) >> 1] = __floats2bfloat162_rn(v2, v3);
            }
        }
    }
}

// ---------------------------------------------------------------------------
// Gather v4 (measured best): one 64-thread block per node; thread t owns
// features [4t,4t+4) = one 8B uint2 of bf16x2 per edge; smem-staged offsets;
// unroll 8; fp32 accumulation.  Epilogue resets g_cur for the next call.
__global__ void gather_kernel() {
    const int n = blockIdx.x;
    const int t = threadIdx.x;        // 0..63
    const int deg = g_cur[n];
    const int base = n << 8;

    __shared__ int soff[64];
    float4 acc = make_float4(0.f, 0.f, 0.f, 0.f);
    const uint2* __restrict__ xb = (const uint2*)g_xhb + t;   // row stride 64 uint2

    for (int j0 = 0; j0 < deg; j0 += 64) {
        int m = min(64, deg - j0);
        if (t < m) soff[t] = g_csr[base + j0 + t] << 6;       // row offset in uint2 units
        __syncthreads();
        int j = 0;
        for (; j + 8 <= m; j += 8) {
            uint2 v0 = xb[soff[j]];
            uint2 v1 = xb[soff[j + 1]];
            uint2 v2 = xb[soff[j + 2]];
            uint2 v3 = xb[soff[j + 3]];
            uint2 v4 = xb[soff[j + 4]];
            uint2 v5 = xb[soff[j + 5]];
            uint2 v6 = xb[soff[j + 6]];
            uint2 v7 = xb[soff[j + 7]];
#pragma unroll
            for (int u = 0; u < 8; u++) {
                uint2 v = (u == 0) ? v0 : (u == 1) ? v1 : (u == 2) ? v2 : (u == 3) ? v3
                        : (u == 4) ? v4 : (u == 5) ? v5 : (u == 6) ? v6 : v7;
                float2 f0 = __bfloat1622float2(*(const __nv_bfloat162*)&v.x);
                float2 f1 = __bfloat1622float2(*(const __nv_bfloat162*)&v.y);
                acc.x += f0.x; acc.y += f0.y; acc.z += f1.x; acc.w += f1.y;
            }
        }
        for (; j < m; j++) {
            uint2 v = xb[soff[j]];
            float2 f0 = __bfloat1622float2(*(const __nv_bfloat162*)&v.x);
            float2 f1 = __bfloat1622float2(*(const __nv_bfloat162*)&v.y);
            acc.x += f0.x; acc.y += f0.y; acc.z += f1.x; acc.w += f1.y;
        }
        __syncthreads();
    }
    float inv = 1.f / fmaxf((float)deg, 1.f);
    acc.x *= inv; acc.y *= inv; acc.z *= inv; acc.w *= inv;
    *(float4*)(g_agg + n * H1 + 4 * t) = acc;
    if (t == 0) g_cur[n] = 0;                  // reset for next invocation
}

// ---------------------------------------------------------------------------
// GEMM2 (tf32): only the 3 LIVE gates (i, c, o).  Packed 3000 x 384.
// 64x64x32 tile, double-buffered.  B staged with float4 LDG along the
// contiguous o-dim + STS.128 into the [k][n] smem layout.
__global__ void gemm2_kernel(const float* __restrict__ Wrel,
                             const float* __restrict__ Wroot,
                             const float* __restrict__ bx,
                             const float* __restrict__ bh) {
    __shared__ unsigned As[2 * A_TILE];
    __shared__ unsigned Bs[2 * B_TILE2];
    const int bm = blockIdx.y * 64;
    const int bn = blockIdx.x * 64;                 // packed col block (0..383)
    const int tid = threadIdx.x;
    const int warp = tid >> 5, lane = tid & 31;
    const int wm = warp >> 1, wn = warp & 1;
    const int gid = lane >> 2, tig = lane & 3;
    const int pg = bn >> 7;                         // packed gate 0..2
    const int wg = (pg == 0) ? 0 : pg + 1;          // actual gate 0,2,3
    const int obase = bn & 127;

    float acc[2][4][4];
#pragma unroll
    for (int mt = 0; mt < 2; mt++)
#pragma unroll
        for (int nt = 0; nt < 4; nt++)
#pragma unroll
            for (int r = 0; r < 4; r++) acc[mt][nt][r] = 0.f;

    const int r0 = tid >> 3;        // 0..15 (A row group)
    const int c8 = tid & 7;         // 0..7  (A float4-col)
    const int trow  = tid >> 4;     // 0..7  (B k-row group)
    const int tcol4 = (tid & 15) * 4; // 0..60 (B float4-col)

    float4 ra[4], rbv[4];
#pragma unroll
    for (int rr = 0; rr < 4; rr++) {
        int gm = bm + r0 + rr * 16;
        ra[rr] = make_float4(0.f, 0.f, 0.f, 0.f);
        if (gm < N_PAD)
            ra[rr] = *(const float4*)(g_agg + (size_t)gm * H1 + 4 * c8);
    }
    {
        const float* Wb = Wrel + (size_t)wg * H1 * OUTD + obase;
#pragma unroll
        for (int j = 0; j < 4; j++)
            rbv[j] = *(const float4*)(Wb + (size_t)(trow + j * 8) * OUTD + tcol4);
    }

    for (int k0 = 0; k0 < 2 * H1; k0 += 32) {
        const int buf = (k0 >> 5) & 1;
        unsigned* Ab = As + buf * A_TILE;
        unsigned* Bb = Bs + buf * B_TILE2;
#pragma unroll
        for (int rr = 0; rr < 4; rr++)
            *(uint4*)&Ab[(r0 + rr * 16) * ASTRIDE + 4 * c8] = cvt4(ra[rr]);
#pragma unroll
        for (int j = 0; j < 4; j++)
            *(uint4*)&Bb[(trow + j * 8) * BSTRIDE2 + tcol4] = cvt4(rbv[j]);
        __syncthreads();
        if (k0 + 32 < 2 * H1) {
            int kn = k0 + 32;
            const float* Abase = (kn < H1) ? (g_agg + kn) : (g_xh + (kn - H1));
#pragma unroll
            for (int rr = 0; rr < 4; rr++) {
                int gm = bm + r0 + rr * 16;
                ra[rr] = make_float4(0.f, 0.f, 0.f, 0.f);
                if (gm < N_PAD)
                    ra[rr] = *(const float4*)(Abase + (size_t)gm * H1 + 4 * c8);
            }
            const float* Wb = (kn < H1)
                ? (Wrel  + (size_t)wg * H1 * OUTD + (size_t)kn * OUTD + obase)
                : (Wroot + (size_t)wg * H1 * OUTD + (size_t)(kn - H1) * OUTD + obase);
#pragma unroll
            for (int j = 0; j < 4; j++)
                rbv[j] = *(const float4*)(Wb + (size_t)(trow + j * 8) * OUTD + tcol4);
        }

#pragma unroll
        for (int ks = 0; ks < 4; ks++) {
            int kk = ks * 8;
            unsigned a[2][4], b[4][2];
#pragma unroll
            for (int mt = 0; mt < 2; mt++) {
                int ar = wm * 32 + mt * 16;
                a[mt][0] = Ab[(ar + gid) * ASTRIDE + kk + tig];
                a[mt][1] = Ab[(ar + gid + 8) * ASTRIDE + kk + tig];
                a[mt][2] = Ab[(ar + gid) * ASTRIDE + kk + tig + 4];
                a[mt][3] = Ab[(ar + gid + 8) * ASTRIDE + kk + tig + 4];
            }
#pragma unroll
            for (int nt = 0; nt < 4; nt++) {
                int nc = wn * 32 + nt * 8 + gid;
                b[nt][0] = Bb[(kk + tig) * BSTRIDE2 + nc];
                b[nt][1] = Bb[(kk + tig + 4) * BSTRIDE2 + nc];
            }
#pragma unroll
            for (int mt = 0; mt < 2; mt++)
#pragma unroll
                for (int nt = 0; nt < 4; nt++)
                    mma_tf32(acc[mt][nt], a[mt], b[nt]);
        }
    }

#pragma unroll
    for (int mt = 0; mt < 2; mt++) {
        int mrow0 = bm + wm * 32 + mt * 16 + gid;
#pragma unroll
        for (int nt = 0; nt < 4; nt++) {
            int ncol = bn + wn * 32 + nt * 8 + 2 * tig;      // packed col
            int wcol0 = wg * OUTD + (ncol & 127);            // weight-space col
            float b0 = bx[wcol0] + bh[wcol0];
            float b1 = bx[wcol0 + 1] + bh[wcol0 + 1];
            if (mrow0 < N_PAD) {
                g_gate[(size_t)mrow0 * GATES_N + ncol]     = acc[mt][nt][0] + b0;
                g_gate[(size_t)mrow0 * GATES_N + ncol + 1] = acc[mt][nt][1] + b1;
            }
            if (mrow0 + 8 < N_PAD) {
                g_gate[(size_t)(mrow0 + 8) * GATES_N + ncol]     = acc[mt][nt][2] + b0;
                g_gate[(size_t)(mrow0 + 8) * GATES_N + ncol + 1] = acc[mt][nt][3] + b1;
            }
        }
    }
}

// ---------------------------------------------------------------------------
// Gates + H + final projection.  Packed gates: [i | c | o] stride 384.
__global__ void finish_kernel(const float* __restrict__ fcw,
                              const float* __restrict__ fcb,
                              float* __restrict__ out,
                              float* __restrict__ Hout) {
    int n = blockIdx.x;       // 0..2999
    int o = threadIdx.x;      // 0..127
    const float* g = g_gate + (size_t)n * GATES_N;
    float gi = g[o];
    float gc = g[OUTD + o];
    float go = g[2 * OUTD + o];
    float I = 1.f / (1.f + __expf(-gi));
    float T = tanhf(gc);
    float O = 1.f / (1.f + __expf(-go));
    float C = I * T;
    float H = O * tanhf(C);
    Hout[n * OUTD + o] = H;

    float v = H * fcw[o];
#pragma unroll
    for (int s = 16; s > 0; s >>= 1)
        v += __shfl_down_sync(0xffffffffu, v, s);
    __shared__ float sred[4];
    if ((o & 31) == 0) sred[o >> 5] = v;
    __syncthreads();
    if (o == 0 && n < N_REAL)
        out[n] = sred[0] + sred[1] + sred[2] + sred[3] + fcb[0];
}

// ---------------------------------------------------------------------------
extern "C" void kernel_launch(void* const* d_in, const int* in_sizes, int n_in,
                              void* d_out, int out_size) {
    const float* x      = (const float*)d_in[0];
    const int*   ei     = (const int*)  d_in[1];
    const float* fc0_w  = (const float*)d_in[2];
    const float* fc0_b  = (const float*)d_in[3];
    const float* Wx_rel = (const float*)d_in[4];
    const float* Wx_root= (const float*)d_in[5];
    const float* bx     = (const float*)d_in[6];
    // d_in[7] Wh_rel, d_in[8] Wh_root: multiplied by zero state -> unused
    const float* bh     = (const float*)d_in[9];
    const float* fc_w   = (const float*)d_in[10];
    const float* fc_b   = (const float*)d_in[11];
    const int E = in_sizes[1] / 2;

    float* out  = (float*)d_out;          // [2500]
    float* Hout = out + N_REAL;           // [3000 x 128]

    // CSR build and GEMM1 are data-independent: one fused launch, block-specialized.
    csr_gemm1_kernel<<<CSR_BLOCKS + G1_TILES, 128>>>(x, fc0_w, fc0_b, ei, E);

    gather_kernel<<<N_PAD, 64>>>();

    dim3 g2(GATES_N / 64, (N_PAD + 63) / 64);      // 6 x 47
    gemm2_kernel<<<g2, 128>>>(Wx_rel, Wx_root, bx, bh);

    finish_kernel<<<N_PAD, OUTD>>>(fc_w, fc_b, out, Hout);
}